// round 16
// baseline (speedup 1.0000x reference)
#include <cuda_runtime.h>
#include <cuda_fp16.h>
#include <math.h>
#include <stdint.h>

// ---------------- scratch (uint4 => 16B alignment for cp.async) ----------------
__device__ uint4 g_attn4 [8388608];    // half attn/S (in-place) [4][4096][4096]
__device__ uint4 g_xth4  [3145728];    // half XT hi, 3 inputs x [4][4096][512]
__device__ uint4 g_xtl4  [3145728];    // half XT lo
__device__ uint4 g_wh4   [49152];      // half W hi, 3 x [512][512]
__device__ uint4 g_Fh4   [1048576];    // half F hi [4][4096][512]
__device__ uint4 g_Gh4   [1048576];    // half G hi
__device__ uint4 g_Hcat4 [2097152];    // half Hcat [4][1024][4096], rows interleaved (H[c],H^2[c])
__device__ uint4 g_meanT4[2097152];    // fp32 [4][512][4096]
__device__ uint4 g_stdT4 [2097152];

// ---------------- helpers ----------------
__device__ __forceinline__ uint32_t smem_u32(const void* p) {
    uint32_t a;
    asm("{ .reg .u64 t; cvta.to.shared.u64 t, %1; cvt.u32.u64 %0, t; }" : "=r"(a) : "l"(p));
    return a;
}
__device__ __forceinline__ void cp16(uint32_t dst, const void* src) {
    asm volatile("cp.async.ca.shared.global [%0], [%1], 16;" :: "r"(dst), "l"(src));
}
__device__ __forceinline__ void ldsm4(uint32_t* r, uint32_t addr) {
    asm volatile("ldmatrix.sync.aligned.m8n8.x4.shared.b16 {%0,%1,%2,%3}, [%4];"
        : "=r"(r[0]), "=r"(r[1]), "=r"(r[2]), "=r"(r[3]) : "r"(addr));
}
__device__ __forceinline__ void mma16(float* d, const uint32_t* a, const uint32_t* b) {
    asm volatile("mma.sync.aligned.m16n8k16.row.col.f32.f16.f16.f32 "
        "{%0,%1,%2,%3}, {%4,%5,%6,%7}, {%8,%9}, {%0,%1,%2,%3};"
        : "+f"(d[0]), "+f"(d[1]), "+f"(d[2]), "+f"(d[3])
        : "r"(a[0]), "r"(a[1]), "r"(a[2]), "r"(a[3]), "r"(b[0]), "r"(b[1]));
}

// FMA-only exp (Schraudolph round + deg-6 Taylor of 2^f), rel err ~1.5e-7.
__device__ __forceinline__ float fast_exp(float x) {
    x = fmaxf(x, -80.f);
    float t = x * 1.44269504088896f;
    float z = t + 12582912.f;
    int   i = __float_as_int(z) - 0x4B400000;
    float f = t - (z - 12582912.f);
    float p = 1.53989037e-4f;
    p = fmaf(p, f, 1.33335581e-3f);
    p = fmaf(p, f, 9.61812910e-3f);
    p = fmaf(p, f, 5.55041087e-2f);
    p = fmaf(p, f, 2.40226507e-1f);
    p = fmaf(p, f, 6.93147181e-1f);
    p = fmaf(p, f, 1.0f);
    return __int_as_float(__float_as_int(p) + (i << 23));
}

// FMA-only sqrt via bit-hack rsqrt + 2 Newton iters.
__device__ __forceinline__ float fast_sqrt(float v) {
    float x = fmaxf(v, 1e-30f);
    float xh = 0.5f * x;
    float y = __int_as_float(0x5f375a86 - (__float_as_int(x) >> 1));
    y = y * fmaf(-xh, y * y, 1.5f);
    y = y * fmaf(-xh, y * y, 1.5f);
    return v * y;
}

// ---------------- gemm_core (64x32 warp tile; TERMS=2; used by conv3) ----------------
template<int TERMS, int KCH>
__device__ __forceinline__ void gemm_core(
    const half* Agh, const half* Agl, const half* Bgh, int K,
    uint32_t sb, int tid, int lane, int wm, int wn, float acc[4][4][4])
{
    constexpr uint32_t ST  = KCH * 2 + 16;
    constexpr uint32_t TL  = 128u * ST;
    constexpr uint32_t BUF = (TERMS == 2 ? 3u : 2u) * TL;
    constexpr int LPR = KCH / 8;
    constexpr int PP  = (128 * LPR) / 256;

    auto stage = [&](int ch, int buf) {
        uint32_t base = sb + buf * BUF;
        #pragma unroll
        for (int it = 0; it < PP; it++) {
            int idx = tid + it * 256;
            int r = idx / LPR, f = idx % LPR;
            uint32_t off = r * ST + f * 16;
            size_t go = (size_t)r * K + ch * KCH + f * 8;
            cp16(base + off, Agh + go);
            cp16(base + TL + off, Bgh + go);
            if (TERMS == 2) cp16(base + 2 * TL + off, Agl + go);
        }
        asm volatile("cp.async.commit_group;" ::: "memory");
    };

    const int t8 = lane >> 3, rr = lane & 7;
    const uint32_t a_off = (uint32_t)((t8 & 1) * 8 + rr) * ST + (t8 >> 1) * 16;
    const uint32_t b_off = (uint32_t)((t8 >> 1) * 8 + rr) * ST + (t8 & 1) * 16;

    const int NC = K / KCH;
    stage(0, 0);
    for (int ch = 0; ch < NC; ch++) {
        const int buf = ch & 1;
        if (ch + 1 < NC) {
            stage(ch + 1, buf ^ 1);
            asm volatile("cp.async.wait_group 1;" ::: "memory");
        } else {
            asm volatile("cp.async.wait_group 0;" ::: "memory");
        }
        __syncthreads();

        const uint32_t ab = sb + buf * BUF;
        const uint32_t bb = ab + TL;

        #pragma unroll
        for (int k16 = 0; k16 < KCH / 16; k16++) {
            const uint32_t kb = k16 * 32;
            uint32_t bhf[4][2];
            #pragma unroll
            for (int pr = 0; pr < 2; pr++) {
                uint32_t r4[4];
                ldsm4(r4, bb + (uint32_t)(wn + pr * 16) * ST + b_off + kb);
                bhf[pr * 2][0] = r4[0]; bhf[pr * 2][1] = r4[1];
                bhf[pr * 2 + 1][0] = r4[2]; bhf[pr * 2 + 1][1] = r4[3];
            }
            #pragma unroll
            for (int im = 0; im < 4; im++) {
                uint32_t af[4];
                ldsm4(af, ab + (uint32_t)(wm + im * 16) * ST + a_off + kb);
                #pragma unroll
                for (int jn = 0; jn < 4; jn++)
                    mma16(acc[im][jn], af, bhf[jn]);
                if (TERMS == 2) {
                    uint32_t alf[4];
                    ldsm4(alf, ab + 2 * TL + (uint32_t)(wm + im * 16) * ST + a_off + kb);
                    #pragma unroll
                    for (int jn = 0; jn < 4; jn++)
                        mma16(acc[im][jn], alf, bhf[jn]);
                }
            }
        }
        __syncthreads();
    }
}

// ---------------- fused conv3: all three convs in one launch (unchanged from R15) ----------------
__global__ __launch_bounds__(256, 2) void conv3_kernel(
    const half* __restrict__ XTh, const half* __restrict__ XTl,
    const half* __restrict__ Wh,
    const float* __restrict__ f_b, const float* __restrict__ g_b,
    const float* __restrict__ h_b,
    half* __restrict__ Fh, half* __restrict__ Gh, half* __restrict__ Hcat)
{
    extern __shared__ char smem[];
    const int tid = threadIdx.x, lane = tid & 31, wid = tid >> 5;
    const int inp = blockIdx.z >> 2, b = blockIdx.z & 3;
    const int n0 = blockIdx.x * 128, m0 = blockIdx.y * 128;
    const int K = 512, M = 4096;

    const size_t XN = 4ull * 4096 * 512;
    const half* Agh = XTh + inp * XN + (size_t)b * (4096ull * 512) + (size_t)m0 * K;
    const half* Agl = XTl + inp * XN + (size_t)b * (4096ull * 512) + (size_t)m0 * K;
    const half* Bgh = Wh + (size_t)inp * (512ull * 512) + (size_t)n0 * K;
    const float* bias = (inp == 0) ? f_b : (inp == 1) ? g_b : h_b;

    const uint32_t sb = smem_u32(smem);
    const int wm = (wid >> 2) * 64, wn = (wid & 3) * 32;

    float acc[4][4][4];
    #pragma unroll
    for (int i = 0; i < 4; i++)
        #pragma unroll
        for (int j = 0; j < 4; j++)
            #pragma unroll
            for (int r = 0; r < 4; r++) acc[i][j][r] = 0.f;

    gemm_core<2, 64>(Agh, Agl, Bgh, K, sb, tid, lane, wm, wn, acc);

    half* Chf = (inp == 0) ? Fh : Gh;
    #pragma unroll
    for (int im = 0; im < 4; im++) {
        int r = m0 + wm + im * 16 + (lane >> 2);
        #pragma unroll
        for (int jn = 0; jn < 4; jn++) {
            int cc = n0 + wn + jn * 8 + (lane & 3) * 2;
            float b0 = __ldg(&bias[cc]), b1 = __ldg(&bias[cc + 1]);
            float v00 = acc[im][jn][0] + b0, v01 = acc[im][jn][1] + b1;
            float v10 = acc[im][jn][2] + b0, v11 = acc[im][jn][3] + b1;
            if (inp == 2) {
                half* Hc = Hcat + (size_t)b * 1024ull * 4096ull;
                Hc[(size_t)(2 * cc)     * M + r]     = __float2half_rn(v00);
                Hc[(size_t)(2 * cc + 1) * M + r]     = __float2half_rn(v00 * v00);
                Hc[(size_t)(2 * cc + 2) * M + r]     = __float2half_rn(v01);
                Hc[(size_t)(2 * cc + 3) * M + r]     = __float2half_rn(v01 * v01);
                Hc[(size_t)(2 * cc)     * M + r + 8] = __float2half_rn(v10);
                Hc[(size_t)(2 * cc + 1) * M + r + 8] = __float2half_rn(v10 * v10);
                Hc[(size_t)(2 * cc + 2) * M + r + 8] = __float2half_rn(v11);
                Hc[(size_t)(2 * cc + 3) * M + r + 8] = __float2half_rn(v11 * v11);
            } else {
                size_t o0 = (size_t)b * (4096ull * 512) + (size_t)r * 512 + cc;
                size_t o1 = o0 + (size_t)8 * 512;
                *(half2*)(Chf + o0) = __floats2half2_rn(v00, v01);
                *(half2*)(Chf + o1) = __floats2half2_rn(v10, v11);
            }
        }
    }
}

// ---------------- wide GEMM (TERMS=1): block 128m x 256n, warp tile 64x64 ----------------
// 8 warps (2m x 4n), 1 CTA/SM. OUTM: 1=half out, 3=mean/std direct.
template<int KCH, int OUTM>
__global__ __launch_bounds__(256, 1) void gemm1w(
    const half* __restrict__ Ah, const half* __restrict__ Bh,
    float* __restrict__ Cf, float* __restrict__ Cf2, half* __restrict__ Chf,
    int M, int N, int K, size_t sA, size_t sB)
{
    extern __shared__ char smem[];
    const int tid = threadIdx.x, lane = tid & 31, wid = tid >> 5;
    const int b = blockIdx.z;
    const int n0 = blockIdx.x * 256, m0 = blockIdx.y * 128;
    const half* Agh = Ah + (size_t)b * sA + (size_t)m0 * K;
    const half* Bgh = Bh + (size_t)b * sB + (size_t)n0 * K;

    const uint32_t sb = smem_u32(smem);
    constexpr uint32_t ST  = KCH * 2 + 16;
    constexpr uint32_t TLA = 128u * ST;
    constexpr uint32_t TLB = 256u * ST;
    constexpr uint32_t BUF = TLA + TLB;
    constexpr int LPR = KCH / 8;
    constexpr int PPA = (128 * LPR) / 256;
    constexpr int PPB = (256 * LPR) / 256;

    const int wm = (wid >> 2) * 64, wn = (wid & 3) * 64;

    float acc[4][8][4];
    #pragma unroll
    for (int i = 0; i < 4; i++)
        #pragma unroll
        for (int j = 0; j < 8; j++)
            #pragma unroll
            for (int r = 0; r < 4; r++) acc[i][j][r] = 0.f;

    auto stage = [&](int ch, int buf) {
        uint32_t base = sb + buf * BUF;
        #pragma unroll
        for (int it = 0; it < PPA; it++) {
            int idx = tid + it * 256;
            int r = idx / LPR, f = idx % LPR;
            cp16(base + r * ST + f * 16, Agh + (size_t)r * K + ch * KCH + f * 8);
        }
        #pragma unroll
        for (int it = 0; it < PPB; it++) {
            int idx = tid + it * 256;
            int r = idx / LPR, f = idx % LPR;
            cp16(base + TLA + r * ST + f * 16, Bgh + (size_t)r * K + ch * KCH + f * 8);
        }
        asm volatile("cp.async.commit_group;" ::: "memory");
    };

    const int t8 = lane >> 3, rr = lane & 7;
    const uint32_t a_off = (uint32_t)((t8 & 1) * 8 + rr) * ST + (t8 >> 1) * 16;
    const uint32_t b_off = (uint32_t)((t8 >> 1) * 8 + rr) * ST + (t8 & 1) * 16;

    const int NC = K / KCH;
    stage(0, 0);
    for (int ch = 0; ch < NC; ch++) {
        const int buf = ch & 1;
        if (ch + 1 < NC) {
            stage(ch + 1, buf ^ 1);
            asm volatile("cp.async.wait_group 1;" ::: "memory");
        } else {
            asm volatile("cp.async.wait_group 0;" ::: "memory");
        }
        __syncthreads();

        const uint32_t ab = sb + buf * BUF;
        const uint32_t bb = ab + TLA;

        #pragma unroll
        for (int k16 = 0; k16 < KCH / 16; k16++) {
            const uint32_t kb = k16 * 32;
            uint32_t bhf[8][2];
            #pragma unroll
            for (int pr = 0; pr < 4; pr++) {
                uint32_t r4[4];
                ldsm4(r4, bb + (uint32_t)(wn + pr * 16) * ST + b_off + kb);
                bhf[pr * 2][0] = r4[0]; bhf[pr * 2][1] = r4[1];
                bhf[pr * 2 + 1][0] = r4[2]; bhf[pr * 2 + 1][1] = r4[3];
            }
            #pragma unroll
            for (int im = 0; im < 4; im++) {
                uint32_t af[4];
                ldsm4(af, ab + (uint32_t)(wm + im * 16) * ST + a_off + kb);
                #pragma unroll
                for (int jn = 0; jn < 8; jn++)
                    mma16(acc[im][jn], af, bhf[jn]);
            }
        }
        __syncthreads();
    }

    // epilogue
    #pragma unroll
    for (int im = 0; im < 4; im++) {
        int r = m0 + wm + im * 16 + (lane >> 2);
        #pragma unroll
        for (int jn = 0; jn < 8; jn++) {
            int cc = n0 + wn + jn * 8 + (lane & 3) * 2;
            float v00 = acc[im][jn][0], v01 = acc[im][jn][1];
            float v10 = acc[im][jn][2], v11 = acc[im][jn][3];
            if constexpr (OUTM == 3) {
                size_t base = ((size_t)b * (N >> 1) + (cc >> 1)) * (size_t)M;
                Cf [base + r]     = v00;
                Cf2[base + r]     = fast_sqrt(fmaxf(v01 - v00 * v00, 0.f));
                Cf [base + r + 8] = v10;
                Cf2[base + r + 8] = fast_sqrt(fmaxf(v11 - v10 * v10, 0.f));
            } else {
                size_t o0 = (size_t)b * (size_t)M * N + (size_t)r * N + cc;
                size_t o1 = o0 + (size_t)8 * N;
                *(half2*)(Chf + o0) = __floats2half2_rn(v00, v01);
                *(half2*)(Chf + o1) = __floats2half2_rn(v10, v11);
            }
        }
    }
}

// ---------------- transpose+split: fp32 -> hi/lo half, all inputs/batches ----------------
__global__ void transpose_split_all(const float* __restrict__ s0, const float* __restrict__ s1,
                                    const float* __restrict__ s2,
                                    half* __restrict__ dh, half* __restrict__ dl)
{
    __shared__ float t[32][33];
    int inp = blockIdx.z >> 2;
    int b = blockIdx.z & 3;
    const float* src = (inp == 0) ? s0 : (inp == 1) ? s1 : s2;
    const float* s = src + (size_t)b * 512ull * 4096ull;
    size_t dbo = ((size_t)inp * 4 + b) * 512ull * 4096ull;
    int c0 = blockIdx.x * 32, r0 = blockIdx.y * 32;
    int tx = threadIdx.x, ty = threadIdx.y;
    int tid = ty * 32 + tx;
    #pragma unroll
    for (int k = 0; k < 4; k++)
        t[ty + k * 8][tx] = s[(size_t)(r0 + ty + k * 8) * 4096 + c0 + tx];
    __syncthreads();
    #pragma unroll
    for (int ps = 0; ps < 2; ps++) {
        int idx = tid + ps * 256;
        int rr = idx >> 4;
        int cp = idx & 15;
        float v0 = t[2 * cp][rr];
        float v1 = t[2 * cp + 1][rr];
        size_t o = dbo + (size_t)(c0 + rr) * 512 + r0 + 2 * cp;
        half h0 = __float2half_rn(v0), h1 = __float2half_rn(v1);
        *(half2*)(dh + o) = half2(h0, h1);
        *(half2*)(dl + o) = half2(__float2half_rn(v0 - __half2float(h0)),
                                  __float2half_rn(v1 - __half2float(h1)));
    }
}

__global__ void weights_to_half(const float* __restrict__ w0, const float* __restrict__ w1,
                                const float* __restrict__ w2, half* __restrict__ wh)
{
    const float* w = (blockIdx.y == 0) ? w0 : (blockIdx.y == 1) ? w1 : w2;
    int i = blockIdx.x * 256 + threadIdx.x;
    wh[(size_t)blockIdx.y * 262144 + i] = __float2half_rn(w[i]);
}

// ---------------- block reductions ----------------
__device__ __forceinline__ float block_reduce_max(float v, float* red) {
    #pragma unroll
    for (int o = 16; o > 0; o >>= 1) v = fmaxf(v, __shfl_xor_sync(0xffffffffu, v, o));
    int wid = threadIdx.x >> 5, lid = threadIdx.x & 31;
    if (lid == 0) red[wid] = v;
    __syncthreads();
    if (wid == 0) {
        v = (lid < 8) ? red[lid] : -1e30f;
        #pragma unroll
        for (int o = 4; o > 0; o >>= 1) v = fmaxf(v, __shfl_xor_sync(0xffffffffu, v, o));
        if (lid == 0) red[0] = v;
    }
    __syncthreads();
    float r = red[0];
    __syncthreads();
    return r;
}
__device__ __forceinline__ float block_reduce_sum(float v, float* red) {
    #pragma unroll
    for (int o = 16; o > 0; o >>= 1) v += __shfl_xor_sync(0xffffffffu, v, o);
    int wid = threadIdx.x >> 5, lid = threadIdx.x & 31;
    if (lid == 0) red[wid] = v;
    __syncthreads();
    if (wid == 0) {
        v = (lid < 8) ? red[lid] : 0.f;
        #pragma unroll
        for (int o = 4; o > 0; o >>= 1) v += __shfl_xor_sync(0xffffffffu, v, o);
        if (lid == 0) red[0] = v;
    }
    __syncthreads();
    float r = red[0];
    __syncthreads();
    return r;
}
__device__ __forceinline__ void block_reduce_sum2(float& a, float& b, float* red) {
    #pragma unroll
    for (int o = 16; o > 0; o >>= 1) {
        a += __shfl_xor_sync(0xffffffffu, a, o);
        b += __shfl_xor_sync(0xffffffffu, b, o);
    }
    int wid = threadIdx.x >> 5, lid = threadIdx.x & 31;
    if (lid == 0) { red[wid] = a; red[32 + wid] = b; }
    __syncthreads();
    if (wid == 0) {
        a = (lid < 8) ? red[lid] : 0.f;
        b = (lid < 8) ? red[32 + lid] : 0.f;
        #pragma unroll
        for (int o = 4; o > 0; o >>= 1) {
            a += __shfl_xor_sync(0xffffffffu, a, o);
            b += __shfl_xor_sync(0xffffffffu, b, o);
        }
        if (lid == 0) { red[0] = a; red[32] = b; }
    }
    __syncthreads();
    a = red[0]; b = red[32];
    __syncthreads();
}
__device__ __forceinline__ void block_reduce_sum3(float& a, float& b, float& c, float* red) {
    #pragma unroll
    for (int o = 16; o > 0; o >>= 1) {
        a += __shfl_xor_sync(0xffffffffu, a, o);
        b += __shfl_xor_sync(0xffffffffu, b, o);
        c += __shfl_xor_sync(0xffffffffu, c, o);
    }
    int wid = threadIdx.x >> 5, lid = threadIdx.x & 31;
    if (lid == 0) { red[wid] = a; red[32 + wid] = b; red[64 + wid] = c; }
    __syncthreads();
    if (wid == 0) {
        a = (lid < 8) ? red[lid] : 0.f;
        b = (lid < 8) ? red[32 + lid] : 0.f;
        c = (lid < 8) ? red[64 + lid] : 0.f;
        #pragma unroll
        for (int o = 4; o > 0; o >>= 1) {
            a += __shfl_xor_sync(0xffffffffu, a, o);
            b += __shfl_xor_sync(0xffffffffu, b, o);
            c += __shfl_xor_sync(0xffffffffu, c, o);
        }
        if (lid == 0) { red[0] = a; red[32] = b; red[64] = c; }
    }
    __syncthreads();
    a = red[0]; b = red[32]; c = red[64];
    __syncthreads();
}

// ---------------- softmax mix: register-resident, half in/out, IN PLACE ----------------
__global__ __launch_bounds__(256) void softmax_mix_kernel(
    half* __restrict__ attn, const float* __restrict__ w_mix)
{
    __shared__ float red[96];
    half* p = attn + (size_t)blockIdx.x * 4096;
    int tid = threadIdx.x;

    uint4 u0 = ((const uint4*)p)[tid * 2];
    uint4 u1 = ((const uint4*)p)[tid * 2 + 1];
    float v[16];
    {
        const half2* h0 = (const half2*)&u0;
        const half2* h1 = (const half2*)&u1;
        #pragma unroll
        for (int k = 0; k < 4; k++) {
            float2 f0 = __half22float2(h0[k]);
            float2 f1 = __half22float2(h1[k]);
            v[2 * k] = f0.x; v[2 * k + 1] = f0.y;
            v[8 + 2 * k] = f1.x; v[8 + 2 * k + 1] = f1.y;
        }
    }

    float lmax = -1e30f;
    #pragma unroll
    for (int k = 0; k < 16; k++) lmax = fmaxf(lmax, v[k]);
    float m1 = block_reduce_max(lmax, red);
    float m2 = fmaxf(m1, 0.f);
    float Cneg = fast_exp(-m2);

    float z1 = 0.f, z2p = 0.f, nneg = 0.f;
    #pragma unroll
    for (int k = 0; k < 16; k++) {
        float x = v[k];
        float e1 = fast_exp(x - m1);
        bool pos = x > 0.f;
        z1 += e1;
        if (pos) z2p += e1; else nneg += 1.f;
        v[k] = pos ? e1 : -e1;
    }
    block_reduce_sum3(z1, z2p, nneg, red);
    float Z1 = z1;
    float Z2 = z2p + nneg * Cneg;

    float ew0 = fast_exp(w_mix[0]), ew1 = fast_exp(w_mix[1]);
    float inv = 1.f / (ew0 + ew1);
    float iz1 = (ew0 * inv) / Z1;
    float iz2 = (ew1 * inv) / Z2;
    float Cn2 = Cneg * iz2;

    float za = 0.f;
    #pragma unroll
    for (int k = 0; k < 16; k++) {
        float se = v[k];
        float e1 = fabsf(se);
        float A = (se > 0.f) ? e1 * (iz1 + iz2) : fmaf(e1, iz1, Cn2);
        float e = fast_exp(A);
        v[k] = e;
        za += e;
    }
    float ZA = block_reduce_sum(za, red);
    float izA = 1.f / ZA;

    half2 o[8];
    #pragma unroll
    for (int k = 0; k < 8; k++)
        o[k] = __floats2half2_rn(v[2 * k] * izA, v[2 * k + 1] * izA);
    ((uint4*)p)[tid * 2]     = *(uint4*)&o[0];
    ((uint4*)p)[tid * 2 + 1] = *(uint4*)&o[4];
}

// ---------------- finalize (register-resident): out = stdT * mvn(content) + meanT ----------------
__global__ __launch_bounds__(256) void finalize_kernel(
    const float* __restrict__ content, const float* __restrict__ meanT,
    const float* __restrict__ stdT, float* __restrict__ out)
{
    __shared__ float red[64];
    int c = blockIdx.x, b = blockIdx.y;
    size_t off = ((size_t)b * 512 + c) * 4096;
    const float4* x4 = (const float4*)(content + off);
    int tid = threadIdx.x;

    float v[16];
    float s = 0.f, ss = 0.f;
    #pragma unroll
    for (int k = 0; k < 4; k++) {
        float4 f = x4[tid * 4 + k];
        v[4 * k] = f.x; v[4 * k + 1] = f.y; v[4 * k + 2] = f.z; v[4 * k + 3] = f.w;
        s += f.x + f.y + f.z + f.w;
        ss += f.x * f.x + f.y * f.y + f.z * f.z + f.w * f.w;
    }
    block_reduce_sum2(s, ss, red);
    float mu = s * (1.f / 4096.f);
    float var = (ss - 4096.f * mu * mu) * (1.f / 4095.f);
    float rstd = rsqrtf(var + 1e-5f);

    const float4* m4 = (const float4*)(meanT + off);
    const float4* s4 = (const float4*)(stdT + off);
    float4* o4 = (float4*)(out + off);
    #pragma unroll
    for (int k = 0; k < 4; k++) {
        float4 mn = m4[tid * 4 + k];
        float4 sd = s4[tid * 4 + k];
        float4 o;
        o.x = sd.x * ((v[4 * k]     - mu) * rstd) + mn.x;
        o.y = sd.y * ((v[4 * k + 1] - mu) * rstd) + mn.y;
        o.z = sd.z * ((v[4 * k + 2] - mu) * rstd) + mn.z;
        o.w = sd.w * ((v[4 * k + 3] - mu) * rstd) + mn.w;
        o4[tid * 4 + k] = o;
    }
}

// ---------------- launch ----------------
extern "C" void kernel_launch(void* const* d_in, const int* in_sizes, int n_in,
                              void* d_out, int out_size)
{
    const float* content     = (const float*)d_in[0];
    const float* style       = (const float*)d_in[1];
    const float* content_key = (const float*)d_in[2];
    const float* style_key   = (const float*)d_in[3];
    const float* f_w = (const float*)d_in[4];
    const float* f_b = (const float*)d_in[5];
    const float* g_w = (const float*)d_in[6];
    const float* g_b = (const float*)d_in[7];
    const float* h_w = (const float*)d_in[8];
    const float* h_b = (const float*)d_in[9];
    const float* w_mix = (const float*)d_in[10];
    float* out = (float*)d_out;

    void *p;
    cudaGetSymbolAddress(&p, g_attn4);  half*  attn = (half*)p;   // logits & S, in place
    cudaGetSymbolAddress(&p, g_xth4);   half*  XTh  = (half*)p;
    cudaGetSymbolAddress(&p, g_xtl4);   half*  XTl  = (half*)p;
    cudaGetSymbolAddress(&p, g_wh4);    half*  Wh   = (half*)p;
    cudaGetSymbolAddress(&p, g_Fh4);    half*  Fh   = (half*)p;
    cudaGetSymbolAddress(&p, g_Gh4);    half*  Gh   = (half*)p;
    cudaGetSymbolAddress(&p, g_Hcat4);  half*  Hcat = (half*)p;
    cudaGetSymbolAddress(&p, g_meanT4); float* meanT= (float*)p;
    cudaGetSymbolAddress(&p, g_stdT4);  float* stdT = (float*)p;

    const int SM2 = 2 * 3 * (128 * 144);          // 110592 — conv3 (TERMS=2, KCH=64)
    const int SMW = 2 * (128 + 256) * 144;        // 110592 — wide TERMS=1 GEMMs
    cudaFuncSetAttribute(conv3_kernel, cudaFuncAttributeMaxDynamicSharedMemorySize, SM2);
    cudaFuncSetAttribute((gemm1w<64,1>), cudaFuncAttributeMaxDynamicSharedMemorySize, SMW);
    cudaFuncSetAttribute((gemm1w<64,3>), cudaFuncAttributeMaxDynamicSharedMemorySize, SMW);

    // prep (2 launches)
    weights_to_half<<<dim3(1024, 3), 256>>>(f_w, g_w, h_w, Wh);
    transpose_split_all<<<dim3(128, 16, 12), dim3(32, 8)>>>(content_key, style_key, style,
                                                            XTh, XTl);

    // all three convs in ONE launch (fp16 2-term); F,G -> half hi; H -> Hcat
    conv3_kernel<<<dim3(4, 32, 12), 256, SM2>>>(XTh, XTl, Wh, f_b, g_b, h_b, Fh, Gh, Hcat);

    // attention logits (fp16 1-term, 64x64 warp tile) -> half attn buffer
    gemm1w<64,1><<<dim3(16, 32, 4), 256, SMW>>>(Fh, Gh, nullptr, nullptr, attn,
        4096, 4096, 512, 4096ull * 512, 4096ull * 512);

    // triple-softmax mix, in place (register-resident)
    softmax_mix_kernel<<<16384, 256>>>(attn, w_mix);

    // mean/second GEMM (fp16, 64x64 warp tile) -> meanT/stdT directly
    gemm1w<64,3><<<dim3(4, 32, 4), 256, SMW>>>(attn, Hcat, meanT, stdT, nullptr,
        4096, 1024, 4096, 4096ull * 4096, 1024ull * 4096);

    // finalize (register-resident)
    finalize_kernel<<<dim3(512, 4), 256>>>(content, meanT, stdT, out);
}